// round 12
// baseline (speedup 1.0000x reference)
#include <cuda_runtime.h>
#include <cuda_fp16.h>
#include <cstdint>

// B=4,S=1024,D=1024,N=32,R=128 -> T=4096 tokens.
// Stage1: h[t,r]   = sum_n fw[t,n] * (x[t,:] . FK[n,:,r])   weighted atomic drains
// build:  A2[t, n*128+r] = rw[t,n]*h[t,r]  (split fp16 hi/lo)
// Stage2: out[t,d] = A2[t,:] . RKflat[:,d]  atomic drains into zeroed out
// fp16 2-product split: a*b ~= ah*b + al*b, fp32 accum.
// R11/R12: persistent CTAs (grid=296), flat global-tile pipeline across work items ->
//      no wave quantization, pipeline never drains. Inner loop identical to R9.
//      (R12 = identical resubmit; R11 bench failed on infra, not kernel.)

#define TOK 4096
#define GRID_P 296          // 2 CTAs/SM x 148 SMs

// ---- static device scratch ----
__device__ __half g_xh[TOK * 1024],   g_xl[TOK * 1024];    // x split hi/lo
__device__ __half g_fk[32768 * 128];                       // FK flat [k][r] fp16
__device__ __half g_rk[4096 * 1024];                       // RK flat [k][d] fp16
__device__ float  g_h[TOK * 128];                          // h (fp32, atomic accum)
__device__ __half g_a2h[TOK * 4096],  g_a2l[TOK * 4096];   // A2 split hi/lo

// ---- helpers ----
__device__ __forceinline__ uint32_t smem_u32(const void* p) {
    uint32_t a;
    asm("{ .reg .u64 t; cvta.to.shared.u64 t, %1; cvt.u32.u64 %0, t; }" : "=r"(a) : "l"(p));
    return a;
}
__device__ __forceinline__ void cp16(uint32_t dst, const void* src) {
    asm volatile("cp.async.cg.shared.global [%0], [%1], 16;" :: "r"(dst), "l"(src));
}
__device__ __forceinline__ void cp_commit() { asm volatile("cp.async.commit_group;" ::: "memory"); }
__device__ __forceinline__ void cp_wait1()  { asm volatile("cp.async.wait_group 1;" ::: "memory"); }

__device__ __forceinline__ void ldsm_x4(uint32_t* r, uint32_t addr) {
    asm volatile("ldmatrix.sync.aligned.m8n8.x4.shared.b16 {%0,%1,%2,%3}, [%4];"
                 : "=r"(r[0]), "=r"(r[1]), "=r"(r[2]), "=r"(r[3]) : "r"(addr));
}
__device__ __forceinline__ void ldsm_x4_t(uint32_t* r, uint32_t addr) {
    asm volatile("ldmatrix.sync.aligned.m8n8.x4.trans.shared.b16 {%0,%1,%2,%3}, [%4];"
                 : "=r"(r[0]), "=r"(r[1]), "=r"(r[2]), "=r"(r[3]) : "r"(addr));
}
__device__ __forceinline__ void mma16816(float c[4], const uint32_t a[4], uint32_t b0, uint32_t b1) {
    asm volatile("mma.sync.aligned.m16n8k16.row.col.f32.f16.f16.f32 "
                 "{%0,%1,%2,%3},{%4,%5,%6,%7},{%8,%9},{%0,%1,%2,%3};"
                 : "+f"(c[0]), "+f"(c[1]), "+f"(c[2]), "+f"(c[3])
                 : "r"(a[0]), "r"(a[1]), "r"(a[2]), "r"(a[3]), "r"(b0), "r"(b1));
}
__device__ __forceinline__ void split1h(float v, __half& h, __half& l) {
    h = __float2half_rn(v);
    l = __float2half_rn(v - __half2float(h));
}

// ---- prep kernels ----
__global__ void split_kernel(const float4* __restrict__ in, uint2* __restrict__ oh,
                             uint2* __restrict__ ol, int n4) {
    int i = blockIdx.x * blockDim.x + threadIdx.x;
    if (i >= n4) return;
    float4 v = in[i];
    __half hx, lx, hy, ly, hz, lz, hw, lw;
    split1h(v.x, hx, lx); split1h(v.y, hy, ly); split1h(v.z, hz, lz); split1h(v.w, hw, lw);
    __half2 h01 = __halves2half2(hx, hy), h23 = __halves2half2(hz, hw);
    __half2 l01 = __halves2half2(lx, ly), l23 = __halves2half2(lz, lw);
    uint2 uh, ul;
    uh.x = *reinterpret_cast<uint32_t*>(&h01); uh.y = *reinterpret_cast<uint32_t*>(&h23);
    ul.x = *reinterpret_cast<uint32_t*>(&l01); ul.y = *reinterpret_cast<uint32_t*>(&l23);
    oh[i] = uh; ol[i] = ul;
}

__global__ void conv_kernel(const float4* __restrict__ in, uint2* __restrict__ o, int n4) {
    int i = blockIdx.x * blockDim.x + threadIdx.x;
    if (i >= n4) return;
    float4 v = in[i];
    __half2 h01 = __halves2half2(__float2half_rn(v.x), __float2half_rn(v.y));
    __half2 h23 = __halves2half2(__float2half_rn(v.z), __float2half_rn(v.w));
    uint2 u;
    u.x = *reinterpret_cast<uint32_t*>(&h01); u.y = *reinterpret_cast<uint32_t*>(&h23);
    o[i] = u;
}

__global__ void zero_kernel(float4* __restrict__ p, int n4) {
    int i = blockIdx.x * blockDim.x + threadIdx.x;
    if (i < n4) p[i] = make_float4(0.f, 0.f, 0.f, 0.f);
}

__global__ void build_a2_kernel(const float* __restrict__ h, const float* __restrict__ rw,
                                __half* __restrict__ a2h, __half* __restrict__ a2l) {
    const int t = blockIdx.x, r = threadIdx.x;
    const float hv = h[(size_t)t * 128 + r];
    __shared__ float ws[32];
    if (r < 32) ws[r] = rw[t * 32 + r];
    __syncthreads();
#pragma unroll
    for (int n = 0; n < 32; n++) {
        float v = ws[n] * hv;
        __half hi, lo; split1h(v, hi, lo);
        const size_t o = (size_t)t * 4096 + n * 128 + r;
        a2h[o] = hi; a2l[o] = lo;
    }
}

// ---- Persistent GEMM: BM=128, BN=128, BK=32, 256 thr, 8 warps (4m x 2n), warp 32x64 ----
// Work item = one 128x128 output tile x 256-deep K chunk (TT=8 k-tiles of 32).
// S1 item: m0i = item>>7, kc = item&127; bk0 = kc*256; expert ne = kc>>2; n0 = 0.
//   Drain (weighted atomic into h) when (item&3)==3 at t==7, or at range end.
// S2 item: mn = item>>4 (m0i = mn>>3, n0i = mn&7), kc = item&15; bk0 = kc*256.
//   Drain (atomic into zeroed out) when (item&15)==15 at t==7, or at range end.
#define APITCH 80    // 32 fp16 + 8 pad
#define BPITCH 272   // 128 fp16 + 8 pad
#define OFF_AL 10240
#define OFF_B  20480
#define SSTRIDE 29184  // 20480 + 32*272
#define NSTAGE 3
#define SMEM_TOTAL (NSTAGE * SSTRIDE)   // 87552 -> 2 CTAs/SM
#define TT 8           // k-tiles per item
#define NITEMS 4096    // both stages

template<int NCOLS, int AW, int AMASK, bool S1>
__global__ __launch_bounds__(256, 2)
void gemm_pp(const __half* __restrict__ ah_g, const __half* __restrict__ al_g,
             const __half* __restrict__ b_g,
             const float* __restrict__ wg, float* __restrict__ Cout) {
    extern __shared__ char sm[];
    const uint32_t sb0 = smem_u32(sm);
    const int tid = threadIdx.x, lane = tid & 31, wid = tid >> 5;
    const int wm = (wid >> 1) * 32, wn = (wid & 1) * 64;

    const int lr = lane & 15, lc = (lane >> 4) * 8;
    const int grp = lane >> 2, tig = lane & 3;

    // contiguous item range for this CTA
    const int i0 = (int)(((long long)blockIdx.x * NITEMS) / GRID_P);
    const int i1 = (int)(((long long)(blockIdx.x + 1) * NITEMS) / GRID_P);
    const int QT = (i1 - i0) * TT;

    auto load_tile = [&](int q, int stg) {
        const int item = i0 + (q >> 3);
        const int t = q & 7;
        int m0, n0, bk0;
        if (S1) { m0 = (item >> 7) * 128; n0 = 0; bk0 = (item & 127) * 256; }
        else { const int mn = item >> 4; m0 = (mn >> 3) * 128; n0 = (mn & 7) * 128; bk0 = (item & 15) * 256; }
        const int kg = bk0 + t * 32;
        const uint32_t sb = sb0 + (uint32_t)stg * SSTRIDE;
        const int ac = kg & AMASK;
        // A: 2 chunks/thread per matrix (128 rows x 4 x 16B)
        {
            const int r0 = tid >> 2, k0 = (tid & 3) * 8;
            const int r1 = (tid + 256) >> 2, k1 = ((tid + 256) & 3) * 8;
            const size_t g0 = (size_t)(m0 + r0) * AW + ac + k0;
            const size_t g1 = (size_t)(m0 + r1) * AW + ac + k1;
            cp16(sb + r0 * APITCH + k0 * 2,          ah_g + g0);
            cp16(sb + OFF_AL + r0 * APITCH + k0 * 2, al_g + g0);
            cp16(sb + r1 * APITCH + k1 * 2,          ah_g + g1);
            cp16(sb + OFF_AL + r1 * APITCH + k1 * 2, al_g + g1);
        }
        // B: 2 chunks/thread (32 rows x 16 x 16B)
        {
            const int r0 = tid >> 4, n08 = (tid & 15) * 8;
            const int r1 = (tid + 256) >> 4, n18 = ((tid + 256) & 15) * 8;
            cp16(sb + OFF_B + r0 * BPITCH + n08 * 2, b_g + (size_t)(kg + r0) * NCOLS + n0 + n08);
            cp16(sb + OFF_B + r1 * BPITCH + n18 * 2, b_g + (size_t)(kg + r1) * NCOLS + n0 + n18);
        }
    };

    float P[2][8][4];
#pragma unroll
    for (int mi = 0; mi < 2; mi++)
#pragma unroll
        for (int ni = 0; ni < 8; ni++)
#pragma unroll
            for (int q = 0; q < 4; q++) P[mi][ni][q] = 0.f;

    load_tile(0, 0); cp_commit();
    load_tile(1, 1); cp_commit();

    for (int q = 0; q < QT; q++) {
        cp_wait1();
        __syncthreads();
        if (q + 2 < QT) { load_tile(q + 2, (q + 2) % NSTAGE); }
        cp_commit();

        const uint32_t sb = sb0 + (uint32_t)(q % NSTAGE) * SSTRIDE;
#pragma unroll
        for (int ks = 0; ks < 2; ks++) {
            uint32_t ah[2][4], al_[2][4], bf[4][4];
#pragma unroll
            for (int mi = 0; mi < 2; mi++) {
                const uint32_t aaddr = sb + (uint32_t)(wm + mi * 16 + lr) * APITCH + (ks * 16 + lc) * 2;
                ldsm_x4(ah[mi], aaddr);
                ldsm_x4(al_[mi], aaddr + OFF_AL);
            }
#pragma unroll
            for (int nb = 0; nb < 4; nb++) {
                const uint32_t baddr = sb + OFF_B + (uint32_t)(ks * 16 + lr) * BPITCH
                                       + (wn + nb * 16 + lc) * 2;
                ldsm_x4_t(bf[nb], baddr);
            }
#pragma unroll
            for (int nb = 0; nb < 4; nb++) {
                mma16816(P[0][2 * nb],     ah[0],  bf[nb][0], bf[nb][1]);
                mma16816(P[1][2 * nb],     ah[1],  bf[nb][0], bf[nb][1]);
                mma16816(P[0][2 * nb + 1], ah[0],  bf[nb][2], bf[nb][3]);
                mma16816(P[1][2 * nb + 1], ah[1],  bf[nb][2], bf[nb][3]);
                mma16816(P[0][2 * nb],     al_[0], bf[nb][0], bf[nb][1]);
                mma16816(P[1][2 * nb],     al_[1], bf[nb][0], bf[nb][1]);
                mma16816(P[0][2 * nb + 1], al_[0], bf[nb][2], bf[nb][3]);
                mma16816(P[1][2 * nb + 1], al_[1], bf[nb][2], bf[nb][3]);
            }
        }

        // ---- drain at group boundary or range end (t==7 always at range end) ----
        if ((q & 7) == 7) {
            const int item = i0 + (q >> 3);
            const bool boundary = S1 ? ((item & 3) == 3) : ((item & 15) == 15);
            if (boundary || q == QT - 1) {
                int m0, n0, ne;
                if (S1) { m0 = (item >> 7) * 128; n0 = 0; ne = (item & 127) >> 2; }
                else { const int mn = item >> 4; m0 = (mn >> 3) * 128; n0 = (mn & 7) * 128; ne = 0; }
#pragma unroll
                for (int mi = 0; mi < 2; mi++) {
                    const int rlo = m0 + wm + mi * 16 + grp;
                    float wlo = 1.f, whi = 1.f;
                    if (S1) {
                        wlo = wg[rlo * 32 + ne];
                        whi = wg[(rlo + 8) * 32 + ne];
                    }
#pragma unroll
                    for (int ni = 0; ni < 8; ni++) {
                        const int col = n0 + wn + ni * 8 + tig * 2;
                        float* p0 = Cout + (size_t)rlo * NCOLS + col;
                        float* p1 = Cout + (size_t)(rlo + 8) * NCOLS + col;
                        atomicAdd(p0,     wlo * P[mi][ni][0]);
                        atomicAdd(p0 + 1, wlo * P[mi][ni][1]);
                        atomicAdd(p1,     whi * P[mi][ni][2]);
                        atomicAdd(p1 + 1, whi * P[mi][ni][3]);
                        P[mi][ni][0] = 0.f; P[mi][ni][1] = 0.f;
                        P[mi][ni][2] = 0.f; P[mi][ni][3] = 0.f;
                    }
                }
            }
        }
    }
}

// ---- launch ----
extern "C" void kernel_launch(void* const* d_in, const int* in_sizes, int n_in,
                              void* d_out, int out_size) {
    const float* x  = (const float*)d_in[0];
    const float* fw = (const float*)d_in[1];
    const float* rw = (const float*)d_in[2];
    const float* FK = (const float*)d_in[3];   // (32,1024,128) = [32768][128]
    const float* RK = (const float*)d_in[4];   // (32,128,1024) = [4096][1024]
    float* out = (float*)d_out;

    __half *xh, *xl, *fk, *rk, *a2h, *a2l;
    float* hp;
    cudaGetSymbolAddress((void**)&xh, g_xh);   cudaGetSymbolAddress((void**)&xl, g_xl);
    cudaGetSymbolAddress((void**)&fk, g_fk);   cudaGetSymbolAddress((void**)&rk, g_rk);
    cudaGetSymbolAddress((void**)&a2h, g_a2h); cudaGetSymbolAddress((void**)&a2l, g_a2l);
    cudaGetSymbolAddress((void**)&hp, g_h);

    cudaFuncSetAttribute(gemm_pp<128, 1024, 1023, true>,
                         cudaFuncAttributeMaxDynamicSharedMemorySize, SMEM_TOTAL);
    cudaFuncSetAttribute(gemm_pp<1024, 4096, 4095, false>,
                         cudaFuncAttributeMaxDynamicSharedMemorySize, SMEM_TOTAL);

    zero_kernel<<<512, 256>>>((float4*)hp, TOK * 128 / 4);                            // 0
    split_kernel<<<4096, 256>>>((const float4*)x, (uint2*)xh, (uint2*)xl, 1048576);   // 1
    conv_kernel<<<4096, 256>>>((const float4*)FK, (uint2*)fk, 1048576);               // 2
    // 3: stage-1 persistent GEMM (ncu-sampled slot)
    gemm_pp<128, 1024, 1023, true>
        <<<GRID_P, 256, SMEM_TOTAL>>>(xh, xl, fk, fw, hp);
    conv_kernel<<<4096, 256>>>((const float4*)RK, (uint2*)rk, 1048576);               // 4
    build_a2_kernel<<<TOK, 128>>>(hp, rw, a2h, a2l);                                  // 5
    zero_kernel<<<4096, 256>>>((float4*)out, TOK * 1024 / 4);                         // 6
    // 7: stage-2 persistent GEMM
    gemm_pp<1024, 4096, 4095, false>
        <<<GRID_P, 256, SMEM_TOTAL>>>(a2h, a2l, rk, nullptr, out);
}

// round 13
// speedup vs baseline: 1.6532x; 1.6532x over previous
#include <cuda_runtime.h>
#include <cuda_fp16.h>
#include <cstdint>

// B=4,S=1024,D=1024,N=32,R=128 -> T=4096 tokens.
// Stage1: h[t,r]   = sum_n fw[t,n] * (x[t,:] . FK[n,:,r])  one expert/CTA, weighted atomicAdd
// build:  A2[t, n*128+r] = rw[t,n]*h[t,r]  (single fp16)
// Stage2: out[t,d] = A2[t,:] . RKflat[:,d]  split-K z=4, atomicAdd into zeroed out
// SINGLE-product fp16 GEMMs (a_h*b_h), fp32 accum; weights exact fp32 in epilogue.
// R13: revert persistent (R12 regressed) to R9 z-split grids; 1 product instead of 2.

#define TOK 4096

// ---- static device scratch ----
__device__ __half g_x16[TOK * 1024];     // x fp16
__device__ __half g_fk[32768 * 128];     // FK flat [k][r] fp16
__device__ __half g_rk[4096 * 1024];     // RK flat [k][d] fp16
__device__ float  g_h[TOK * 128];        // h (fp32, atomic accum)
__device__ __half g_a2[TOK * 4096];      // A2 fp16

// ---- helpers ----
__device__ __forceinline__ uint32_t smem_u32(const void* p) {
    uint32_t a;
    asm("{ .reg .u64 t; cvta.to.shared.u64 t, %1; cvt.u32.u64 %0, t; }" : "=r"(a) : "l"(p));
    return a;
}
__device__ __forceinline__ void cp16(uint32_t dst, const void* src) {
    asm volatile("cp.async.cg.shared.global [%0], [%1], 16;" :: "r"(dst), "l"(src));
}
__device__ __forceinline__ void cp_commit() { asm volatile("cp.async.commit_group;" ::: "memory"); }
__device__ __forceinline__ void cp_wait1()  { asm volatile("cp.async.wait_group 1;" ::: "memory"); }

__device__ __forceinline__ void ldsm_x4(uint32_t* r, uint32_t addr) {
    asm volatile("ldmatrix.sync.aligned.m8n8.x4.shared.b16 {%0,%1,%2,%3}, [%4];"
                 : "=r"(r[0]), "=r"(r[1]), "=r"(r[2]), "=r"(r[3]) : "r"(addr));
}
__device__ __forceinline__ void ldsm_x4_t(uint32_t* r, uint32_t addr) {
    asm volatile("ldmatrix.sync.aligned.m8n8.x4.trans.shared.b16 {%0,%1,%2,%3}, [%4];"
                 : "=r"(r[0]), "=r"(r[1]), "=r"(r[2]), "=r"(r[3]) : "r"(addr));
}
__device__ __forceinline__ void mma16816(float c[4], const uint32_t a[4], uint32_t b0, uint32_t b1) {
    asm volatile("mma.sync.aligned.m16n8k16.row.col.f32.f16.f16.f32 "
                 "{%0,%1,%2,%3},{%4,%5,%6,%7},{%8,%9},{%0,%1,%2,%3};"
                 : "+f"(c[0]), "+f"(c[1]), "+f"(c[2]), "+f"(c[3])
                 : "r"(a[0]), "r"(a[1]), "r"(a[2]), "r"(a[3]), "r"(b0), "r"(b1));
}

// ---- prep kernels ----
__global__ void conv_kernel(const float4* __restrict__ in, uint2* __restrict__ o, int n4) {
    int i = blockIdx.x * blockDim.x + threadIdx.x;
    if (i >= n4) return;
    float4 v = in[i];
    __half2 h01 = __halves2half2(__float2half_rn(v.x), __float2half_rn(v.y));
    __half2 h23 = __halves2half2(__float2half_rn(v.z), __float2half_rn(v.w));
    uint2 u;
    u.x = *reinterpret_cast<uint32_t*>(&h01); u.y = *reinterpret_cast<uint32_t*>(&h23);
    o[i] = u;
}

__global__ void zero_kernel(float4* __restrict__ p, int n4) {
    int i = blockIdx.x * blockDim.x + threadIdx.x;
    if (i < n4) p[i] = make_float4(0.f, 0.f, 0.f, 0.f);
}

// A2[t, n*128+r] = half(rw[t,n] * h[t,r]). grid=TOK blocks of 128 threads (r).
__global__ void build_a2_kernel(const float* __restrict__ h, const float* __restrict__ rw,
                                __half* __restrict__ a2) {
    const int t = blockIdx.x, r = threadIdx.x;
    const float hv = h[(size_t)t * 128 + r];
    __shared__ float ws[32];
    if (r < 32) ws[r] = rw[t * 32 + r];
    __syncthreads();
#pragma unroll
    for (int n = 0; n < 32; n++)
        a2[(size_t)t * 4096 + n * 128 + r] = __float2half_rn(ws[n] * hv);
}

// ---- GEMM: BM=128, BN=128, BK=32, 256 thr, 8 warps (4m x 2n), warp tile 32x64 ----
// Single fp16 A and B. 3-stage cp.async pipeline, ONE sync per tile.
// Atomic epilogue; WEIGHTED multiplies by wg[row*32 + bk0>>10].
#define APITCH 80     // 32 fp16 + 8 pad
#define BPITCH 272    // 128 fp16 + 8 pad
#define OFF_B  10240  // A = 128*80
#define SSTRIDE 18944 // 10240 + 32*272
#define NSTAGE 3
#define SMEM_TOTAL (NSTAGE * SSTRIDE)   // 56832 -> 2 CTAs/SM

template<int NCOLS, int AW, int AMASK, int T, bool WEIGHTED>
__global__ __launch_bounds__(256, 2)
void gemm_p(const __half* __restrict__ a_g, const __half* __restrict__ b_g,
            const float* __restrict__ wg, float* __restrict__ Cout) {
    extern __shared__ char sm[];
    const uint32_t sb0 = smem_u32(sm);
    const int tid = threadIdx.x, lane = tid & 31, wid = tid >> 5;
    const int m0 = blockIdx.y * 128;
    const int n0 = blockIdx.x * 128;
    const int bk0 = blockIdx.z * (T * 32);   // absolute K base of this chunk
    const int wm = (wid >> 1) * 32, wn = (wid & 1) * 64;

    const int lr = lane & 15, lc = (lane >> 4) * 8;
    const int grp = lane >> 2, tig = lane & 3;

    auto load_tile = [&](int t, int stg) {
        const int kg = bk0 + t * 32;
        const uint32_t sb = sb0 + (uint32_t)stg * SSTRIDE;
        const int ac = kg & AMASK;
        // A: 512 chunks (128 rows x 4 x 16B), 2 per thread
        {
            const int r0 = tid >> 2, k0 = (tid & 3) * 8;
            const int r1 = (tid + 256) >> 2, k1 = ((tid + 256) & 3) * 8;
            cp16(sb + r0 * APITCH + k0 * 2, a_g + (size_t)(m0 + r0) * AW + ac + k0);
            cp16(sb + r1 * APITCH + k1 * 2, a_g + (size_t)(m0 + r1) * AW + ac + k1);
        }
        // B: 512 chunks (32 rows x 16 x 16B), 2 per thread
        {
            const int r0 = tid >> 4, n08 = (tid & 15) * 8;
            const int r1 = (tid + 256) >> 4, n18 = ((tid + 256) & 15) * 8;
            cp16(sb + OFF_B + r0 * BPITCH + n08 * 2, b_g + (size_t)(kg + r0) * NCOLS + n0 + n08);
            cp16(sb + OFF_B + r1 * BPITCH + n18 * 2, b_g + (size_t)(kg + r1) * NCOLS + n0 + n18);
        }
    };

    float P[2][8][4];
#pragma unroll
    for (int mi = 0; mi < 2; mi++)
#pragma unroll
        for (int ni = 0; ni < 8; ni++)
#pragma unroll
            for (int q = 0; q < 4; q++) P[mi][ni][q] = 0.f;

    load_tile(0, 0); cp_commit();
    load_tile(1, 1); cp_commit();

    for (int t = 0; t < T; t++) {
        cp_wait1();
        __syncthreads();
        if (t + 2 < T) { load_tile(t + 2, (t + 2) % NSTAGE); }
        cp_commit();

        const uint32_t sb = sb0 + (uint32_t)(t % NSTAGE) * SSTRIDE;
#pragma unroll
        for (int ks = 0; ks < 2; ks++) {
            uint32_t ah[2][4], bf[4][4];
#pragma unroll
            for (int mi = 0; mi < 2; mi++)
                ldsm_x4(ah[mi], sb + (uint32_t)(wm + mi * 16 + lr) * APITCH + (ks * 16 + lc) * 2);
#pragma unroll
            for (int nb = 0; nb < 4; nb++)
                ldsm_x4_t(bf[nb], sb + OFF_B + (uint32_t)(ks * 16 + lr) * BPITCH
                                  + (wn + nb * 16 + lc) * 2);
#pragma unroll
            for (int nb = 0; nb < 4; nb++) {
                mma16816(P[0][2 * nb],     ah[0], bf[nb][0], bf[nb][1]);
                mma16816(P[1][2 * nb],     ah[1], bf[nb][0], bf[nb][1]);
                mma16816(P[0][2 * nb + 1], ah[0], bf[nb][2], bf[nb][3]);
                mma16816(P[1][2 * nb + 1], ah[1], bf[nb][2], bf[nb][3]);
            }
        }
    }

    // ---- epilogue: atomic accumulate (weighted for stage 1) ----
#pragma unroll
    for (int mi = 0; mi < 2; mi++) {
        const int rlo = m0 + wm + mi * 16 + grp;
        float wlo = 1.f, whi = 1.f;
        if (WEIGHTED) {
            const int ne = bk0 >> 10;   // T*32 == 1024 per expert
            wlo = wg[rlo * 32 + ne];
            whi = wg[(rlo + 8) * 32 + ne];
        }
#pragma unroll
        for (int ni = 0; ni < 8; ni++) {
            const int col = n0 + wn + ni * 8 + tig * 2;
            float* p0 = Cout + (size_t)rlo * NCOLS + col;
            float* p1 = Cout + (size_t)(rlo + 8) * NCOLS + col;
            atomicAdd(p0,     wlo * P[mi][ni][0]);
            atomicAdd(p0 + 1, wlo * P[mi][ni][1]);
            atomicAdd(p1,     whi * P[mi][ni][2]);
            atomicAdd(p1 + 1, whi * P[mi][ni][3]);
        }
    }
}

// ---- launch ----
extern "C" void kernel_launch(void* const* d_in, const int* in_sizes, int n_in,
                              void* d_out, int out_size) {
    const float* x  = (const float*)d_in[0];
    const float* fw = (const float*)d_in[1];
    const float* rw = (const float*)d_in[2];
    const float* FK = (const float*)d_in[3];   // (32,1024,128) = [32768][128]
    const float* RK = (const float*)d_in[4];   // (32,128,1024) = [4096][1024]
    float* out = (float*)d_out;

    __half *x16, *fk, *rk, *a2;
    float* hp;
    cudaGetSymbolAddress((void**)&x16, g_x16);
    cudaGetSymbolAddress((void**)&fk, g_fk);   cudaGetSymbolAddress((void**)&rk, g_rk);
    cudaGetSymbolAddress((void**)&a2, g_a2);
    cudaGetSymbolAddress((void**)&hp, g_h);

    cudaFuncSetAttribute(gemm_p<128, 1024, 1023, 32, true>,
                         cudaFuncAttributeMaxDynamicSharedMemorySize, SMEM_TOTAL);
    cudaFuncSetAttribute(gemm_p<1024, 4096, 4095, 32, false>,
                         cudaFuncAttributeMaxDynamicSharedMemorySize, SMEM_TOTAL);

    zero_kernel<<<512, 256>>>((float4*)hp, TOK * 128 / 4);                            // 0
    conv_kernel<<<4096, 256>>>((const float4*)x,  (uint2*)x16, 1048576);              // 1
    conv_kernel<<<4096, 256>>>((const float4*)FK, (uint2*)fk, 1048576);               // 2
    // 3: stage-1 GEMM (ncu-sampled slot): one expert per CTA, weighted atomicAdd into h
    gemm_p<128, 1024, 1023, 32, true>
        <<<dim3(1, 32, 32), 256, SMEM_TOTAL>>>(x16, fk, fw, hp);
    conv_kernel<<<4096, 256>>>((const float4*)RK, (uint2*)rk, 1048576);               // 4
    build_a2_kernel<<<TOK, 128>>>(hp, rw, a2);                                        // 5
    zero_kernel<<<4096, 256>>>((float4*)out, TOK * 1024 / 4);                         // 6
    // 7: stage-2 GEMM split-K z=4, atomicAdd into out
    gemm_p<1024, 4096, 4095, 32, false>
        <<<dim3(8, 32, 4), 256, SMEM_TOTAL>>>(a2, rk, nullptr, out);
}

// round 16
// speedup vs baseline: 1.6921x; 1.0235x over previous
#include <cuda_runtime.h>
#include <cuda_fp16.h>
#include <cstdint>

// B=4,S=1024,D=1024,N=32,R=128 -> T=4096 tokens.
// Stage1: h[t,r]   = sum_n fw[t,n] * (x[t,:] . FK[n,:,r])  one expert/CTA, weighted atomicAdd
// build:  A2[t, n*128+r] = rw[t,n]*h[t,r]  (single fp16)
// Stage2: out[t,d] = A2[t,:] . RKflat[:,d]  split-K z=4, atomicAdd into zeroed out
// SINGLE-product fp16 GEMMs, fp32 accum; weights exact fp32 in epilogue.
// R16: 64x64 warp tiles (4 warps, 128 thr) -> SMEM traffic/CTA-tile 64->48 KB, PLUS
//      #pragma unroll 1 on the K loop (suspected full-unroll ptxas blowup caused the
//      R14/R15 container failures; also keeps hot loop inside I-cache L0).

#define TOK 4096

// ---- static device scratch ----
__device__ __half g_x16[TOK * 1024];     // x fp16
__device__ __half g_fk[32768 * 128];     // FK flat [k][r] fp16
__device__ __half g_rk[4096 * 1024];     // RK flat [k][d] fp16
__device__ float  g_h[TOK * 128];        // h (fp32, atomic accum)
__device__ __half g_a2[TOK * 4096];      // A2 fp16

// ---- helpers ----
__device__ __forceinline__ uint32_t smem_u32(const void* p) {
    uint32_t a;
    asm("{ .reg .u64 t; cvta.to.shared.u64 t, %1; cvt.u32.u64 %0, t; }" : "=r"(a) : "l"(p));
    return a;
}
__device__ __forceinline__ void cp16(uint32_t dst, const void* src) {
    asm volatile("cp.async.cg.shared.global [%0], [%1], 16;" :: "r"(dst), "l"(src));
}
__device__ __forceinline__ void cp_commit() { asm volatile("cp.async.commit_group;" ::: "memory"); }
__device__ __forceinline__ void cp_wait1()  { asm volatile("cp.async.wait_group 1;" ::: "memory"); }

__device__ __forceinline__ void ldsm_x4(uint32_t* r, uint32_t addr) {
    asm volatile("ldmatrix.sync.aligned.m8n8.x4.shared.b16 {%0,%1,%2,%3}, [%4];"
                 : "=r"(r[0]), "=r"(r[1]), "=r"(r[2]), "=r"(r[3]) : "r"(addr));
}
__device__ __forceinline__ void ldsm_x4_t(uint32_t* r, uint32_t addr) {
    asm volatile("ldmatrix.sync.aligned.m8n8.x4.trans.shared.b16 {%0,%1,%2,%3}, [%4];"
                 : "=r"(r[0]), "=r"(r[1]), "=r"(r[2]), "=r"(r[3]) : "r"(addr));
}
__device__ __forceinline__ void mma16816(float c[4], const uint32_t a[4], uint32_t b0, uint32_t b1) {
    asm volatile("mma.sync.aligned.m16n8k16.row.col.f32.f16.f16.f32 "
                 "{%0,%1,%2,%3},{%4,%5,%6,%7},{%8,%9},{%0,%1,%2,%3};"
                 : "+f"(c[0]), "+f"(c[1]), "+f"(c[2]), "+f"(c[3])
                 : "r"(a[0]), "r"(a[1]), "r"(a[2]), "r"(a[3]), "r"(b0), "r"(b1));
}

// ---- prep kernels ----
__global__ void conv_kernel(const float4* __restrict__ in, uint2* __restrict__ o, int n4) {
    int i = blockIdx.x * blockDim.x + threadIdx.x;
    if (i >= n4) return;
    float4 v = in[i];
    __half2 h01 = __halves2half2(__float2half_rn(v.x), __float2half_rn(v.y));
    __half2 h23 = __halves2half2(__float2half_rn(v.z), __float2half_rn(v.w));
    uint2 u;
    u.x = *reinterpret_cast<uint32_t*>(&h01); u.y = *reinterpret_cast<uint32_t*>(&h23);
    o[i] = u;
}

__global__ void zero_kernel(float4* __restrict__ p, int n4) {
    int i = blockIdx.x * blockDim.x + threadIdx.x;
    if (i < n4) p[i] = make_float4(0.f, 0.f, 0.f, 0.f);
}

// A2[t, n*128+r] = half(rw[t,n] * h[t,r]). grid=TOK blocks of 128 threads (r).
__global__ void build_a2_kernel(const float* __restrict__ h, const float* __restrict__ rw,
                                __half* __restrict__ a2) {
    const int t = blockIdx.x, r = threadIdx.x;
    const float hv = h[(size_t)t * 128 + r];
    __shared__ float ws[32];
    if (r < 32) ws[r] = rw[t * 32 + r];
    __syncthreads();
#pragma unroll
    for (int n = 0; n < 32; n++)
        a2[(size_t)t * 4096 + n * 128 + r] = __float2half_rn(ws[n] * hv);
}

// ---- GEMM: BM=128, BN=128, BK=32, 128 thr, 4 warps (2m x 2n), warp tile 64x64 ----
// Single fp16 A and B. 3-stage cp.async pipeline, ONE sync per tile, K-loop NOT unrolled.
#define APITCH 80     // 32 fp16 + 8 pad
#define BPITCH 272    // 128 fp16 + 8 pad
#define OFF_B  10240  // A = 128*80
#define SSTRIDE 18944 // 10240 + 32*272
#define NSTAGE 3
#define SMEM_TOTAL (NSTAGE * SSTRIDE)   // 56832 -> 2 CTAs/SM

template<int NCOLS, int AW, int AMASK, int T, bool WEIGHTED>
__global__ __launch_bounds__(128, 2)
void gemm_p(const __half* __restrict__ a_g, const __half* __restrict__ b_g,
            const float* __restrict__ wg, float* __restrict__ Cout) {
    extern __shared__ char sm[];
    const uint32_t sb0 = smem_u32(sm);
    const int tid = threadIdx.x, lane = tid & 31, wid = tid >> 5;
    const int m0 = blockIdx.y * 128;
    const int n0 = blockIdx.x * 128;
    const int bk0 = blockIdx.z * (T * 32);   // absolute K base of this chunk
    const int wm = (wid >> 1) * 64, wn = (wid & 1) * 64;

    const int lr = lane & 15, lc = (lane >> 4) * 8;
    const int grp = lane >> 2, tig = lane & 3;

    auto load_tile = [&](int t, int stg) {
        const int kg = bk0 + t * 32;
        const uint32_t sb = sb0 + (uint32_t)stg * SSTRIDE;
        const int ac = kg & AMASK;
        // A: 512 chunks (128 rows x 4 x 16B), 4 per thread
#pragma unroll
        for (int q = 0; q < 4; q++) {
            const int c = tid + q * 128;
            const int r = c >> 2, k = (c & 3) * 8;
            cp16(sb + r * APITCH + k * 2, a_g + (size_t)(m0 + r) * AW + ac + k);
        }
        // B: 512 chunks (32 rows x 16 x 16B), 4 per thread
#pragma unroll
        for (int q = 0; q < 4; q++) {
            const int c = tid + q * 128;
            const int r = c >> 4, n8 = (c & 15) * 8;
            cp16(sb + OFF_B + r * BPITCH + n8 * 2, b_g + (size_t)(kg + r) * NCOLS + n0 + n8);
        }
    };

    float P[4][8][4];
#pragma unroll
    for (int mi = 0; mi < 4; mi++)
#pragma unroll
        for (int ni = 0; ni < 8; ni++)
#pragma unroll
            for (int q = 0; q < 4; q++) P[mi][ni][q] = 0.f;

    load_tile(0, 0); cp_commit();
    load_tile(1, 1); cp_commit();

#pragma unroll 1
    for (int t = 0; t < T; t++) {
        cp_wait1();
        __syncthreads();
        if (t + 2 < T) { load_tile(t + 2, (t + 2) % NSTAGE); }
        cp_commit();

        const uint32_t sb = sb0 + (uint32_t)(t % NSTAGE) * SSTRIDE;
#pragma unroll
        for (int ks = 0; ks < 2; ks++) {
            uint32_t ah[4][4], bf[4][4];
#pragma unroll
            for (int mi = 0; mi < 4; mi++)
                ldsm_x4(ah[mi], sb + (uint32_t)(wm + mi * 16 + lr) * APITCH + (ks * 16 + lc) * 2);
#pragma unroll
            for (int nb = 0; nb < 4; nb++)
                ldsm_x4_t(bf[nb], sb + OFF_B + (uint32_t)(ks * 16 + lr) * BPITCH
                                  + (wn + nb * 16 + lc) * 2);
#pragma unroll
            for (int nb = 0; nb < 4; nb++)
#pragma unroll
                for (int mi = 0; mi < 4; mi++) {
                    mma16816(P[mi][2 * nb],     ah[mi], bf[nb][0], bf[nb][1]);
                    mma16816(P[mi][2 * nb + 1], ah[mi], bf[nb][2], bf[nb][3]);
                }
        }
    }

    // ---- epilogue: atomic accumulate (weighted for stage 1) ----
#pragma unroll
    for (int mi = 0; mi < 4; mi++) {
        const int rlo = m0 + wm + mi * 16 + grp;
        float wlo = 1.f, whi = 1.f;
        if (WEIGHTED) {
            const int ne = bk0 >> 10;   // T*32 == 1024 per expert
            wlo = wg[rlo * 32 + ne];
            whi = wg[(rlo + 8) * 32 + ne];
        }
#pragma unroll
        for (int ni = 0; ni < 8; ni++) {
            const int col = n0 + wn + ni * 8 + tig * 2;
            float* p0 = Cout + (size_t)rlo * NCOLS + col;
            float* p1 = Cout + (size_t)(rlo + 8) * NCOLS + col;
            atomicAdd(p0,     wlo * P[mi][ni][0]);
            atomicAdd(p0 + 1, wlo * P[mi][ni][1]);
            atomicAdd(p1,     whi * P[mi][ni][2]);
            atomicAdd(p1 + 1, whi * P[mi][ni][3]);
        }
    }
}

// ---- launch ----
extern "C" void kernel_launch(void* const* d_in, const int* in_sizes, int n_in,
                              void* d_out, int out_size) {
    const float* x  = (const float*)d_in[0];
    const float* fw = (const float*)d_in[1];
    const float* rw = (const float*)d_in[2];
    const float* FK = (const float*)d_in[3];   // (32,1024,128) = [32768][128]
    const float* RK = (const float*)d_in[4];   // (32,128,1024) = [4096][1024]
    float* out = (float*)d_out;

    __half *x16, *fk, *rk, *a2;
    float* hp;
    cudaGetSymbolAddress((void**)&x16, g_x16);
    cudaGetSymbolAddress((void**)&fk, g_fk);   cudaGetSymbolAddress((void**)&rk, g_rk);
    cudaGetSymbolAddress((void**)&a2, g_a2);
    cudaGetSymbolAddress((void**)&hp, g_h);

    cudaFuncSetAttribute(gemm_p<128, 1024, 1023, 32, true>,
                         cudaFuncAttributeMaxDynamicSharedMemorySize, SMEM_TOTAL);
    cudaFuncSetAttribute(gemm_p<1024, 4096, 4095, 32, false>,
                         cudaFuncAttributeMaxDynamicSharedMemorySize, SMEM_TOTAL);

    zero_kernel<<<512, 256>>>((float4*)hp, TOK * 128 / 4);                            // 0
    conv_kernel<<<4096, 256>>>((const float4*)x,  (uint2*)x16, 1048576);              // 1
    conv_kernel<<<4096, 256>>>((const float4*)FK, (uint2*)fk, 1048576);               // 2
    // 3: stage-1 GEMM (ncu-sampled slot): one expert per CTA, weighted atomicAdd into h
    gemm_p<128, 1024, 1023, 32, true>
        <<<dim3(1, 32, 32), 128, SMEM_TOTAL>>>(x16, fk, fw, hp);
    conv_kernel<<<4096, 256>>>((const float4*)RK, (uint2*)rk, 1048576);               // 4
    build_a2_kernel<<<TOK, 128>>>(hp, rw, a2);                                        // 5
    zero_kernel<<<4096, 256>>>((float4*)out, TOK * 1024 / 4);                         // 6
    // 7: stage-2 GEMM split-K z=4, atomicAdd into out
    gemm_p<1024, 4096, 4095, 32, false>
        <<<dim3(8, 32, 4), 128, SMEM_TOTAL>>>(a2, rk, nullptr, out);
}